// round 15
// baseline (speedup 1.0000x reference)
#include <cuda_runtime.h>
#include <cuda_bf16.h>

typedef unsigned long long ull;

#define BSZ   16384
#define NF    8
#define TPB   128          // 32 slots × 4 lanes; 4 samples/thread
#define SLOTS 32
#define NS    4
#define SPB   (SLOTS * NS) // 128 samples per block

#define W0_STR 296         // per-net: 8 rows × 36 (16|pad4|16)
#define W1_STR 104         // 8 rows × 12 (8|pad4)
#define W2_STR 272         // 32 rows × 8, +4 skew for rows>=16
#define B2_STR 36

#define OFF_W0 0           // 32*296 = 9472
#define OFF_W1 9472        // 32*104 = 3328
#define OFF_W2 12800       // 32*272 = 8704
#define OFF_B0 21504
#define OFF_B1 21760
#define OFF_B2 22016       // 32*36 = 1152
#define OFF_Y  23168
#define Y_STRIDE 68
#define Y_SI   (SLOTS * Y_STRIDE)   // 2176 floats between sample groups
#define SMEM_FLOATS (OFF_Y + SPB * Y_STRIDE)
#define SMEM_BYTES  (SMEM_FLOATS * 4)

__device__ __forceinline__ ull ffma2u(ull a, ull b, ull c) {
    asm("fma.rn.f32x2 %0, %1, %2, %0;" : "+l"(c) : "l"(a), "l"(b));
    return c;
}
__device__ __forceinline__ ull addx2(ull a, ull b) {
    ull r; asm("add.rn.f32x2 %0, %1, %2;" : "=l"(r) : "l"(a), "l"(b));
    return r;
}
__device__ __forceinline__ ull f2u(float x, float y) {
    ull u; asm("mov.b64 %0, {%1, %2};" : "=l"(u) : "f"(x), "f"(y)); return u;
}
__device__ __forceinline__ void u2ff(ull u, float& x, float& y) {
    asm("mov.b64 {%0, %1}, %2;" : "=f"(x), "=f"(y) : "l"(u));
}
__device__ __forceinline__ void ld4u(const float4* p, ull& u0, ull& u1) {
    float4 v = *p; u0 = f2u(v.x, v.y); u1 = f2u(v.z, v.w);
}
__device__ __forceinline__ float redu(ull u) {
    float x, y; u2ff(u, x, y); return x + y;
}
__device__ __forceinline__ float tanhfast(float x) {
    float r; asm("tanh.approx.f32 %0, %1;" : "=f"(r) : "f"(x));
    return r;
}
__device__ __forceinline__ ull shflxu(ull v, int m) {
    return __shfl_xor_sync(0xFFFFFFFFu, v, m);
}

// ---------------- forward phase -------------------------------------------
// Lane (role, jh): role 0 = t-net, 1 = s-net. State distributed by jh
// (own positions [jh*16, +16) of each vector), replicated across role.
// L0: all 8 rows, partial dot over own 16 inputs, reduce ^1 -> full h1 local.
// L1: all 8 rows, fully local (no exchange). L2: own 16 rows, role-exch ^2.
__device__ __forceinline__ void fwd_phase(const float* __restrict__ sm, int ibT,
                                          const ull (&a)[NS][8], ull (&v)[NS][8],
                                          int role, int jh) {
    const int ib = ibT + role;
    const float* w0 = sm + OFF_W0 + ib * W0_STR + jh * 20;
    const float* w1 = sm + OFF_W1 + ib * W1_STR;
    const float* w2 = sm + OFF_W2 + ib * W2_STR;
    const float* b0 = sm + OFF_B0 + ib * 8;
    const float* b1 = sm + OFF_B1 + ib * 8;
    const float* b2 = sm + OFF_B2 + ib * B2_STR;

    // L0 partial dots
    float pre[NS][8];
#pragma unroll
    for (int j = 0; j < 8; j++) {
        const float4* rp = (const float4*)(w0 + j * 36);
        ull c[8];
        ld4u(rp, c[0], c[1]); ld4u(rp + 1, c[2], c[3]);
        ld4u(rp + 2, c[4], c[5]); ld4u(rp + 3, c[6], c[7]);
#pragma unroll
        for (int si = 0; si < NS; si++) {
            ull m = 0ull;
#pragma unroll
            for (int p = 0; p < 8; p++) m = ffma2u(c[p], a[si][p], m);
            pre[si][j] = redu(m);
        }
    }
    ull h1p[NS][4];
#pragma unroll
    for (int si = 0; si < NS; si++) {
        ull pA = f2u(pre[si][0], pre[si][1]), pB = f2u(pre[si][2], pre[si][3]);
        ull pC = f2u(pre[si][4], pre[si][5]), pD = f2u(pre[si][6], pre[si][7]);
        pA = addx2(pA, shflxu(pA, 1)); pB = addx2(pB, shflxu(pB, 1));
        pC = addx2(pC, shflxu(pC, 1)); pD = addx2(pD, shflxu(pD, 1));
        float s0, s1, s2, s3, s4, s5, s6, s7;
        u2ff(pA, s0, s1); u2ff(pB, s2, s3); u2ff(pC, s4, s5); u2ff(pD, s6, s7);
        h1p[si][0] = f2u(tanhfast(b0[0] + s0), tanhfast(b0[1] + s1));
        h1p[si][1] = f2u(tanhfast(b0[2] + s2), tanhfast(b0[3] + s3));
        h1p[si][2] = f2u(tanhfast(b0[4] + s4), tanhfast(b0[5] + s5));
        h1p[si][3] = f2u(tanhfast(b0[6] + s6), tanhfast(b0[7] + s7));
    }

    // L1 fully local
    float g[NS][8];
#pragma unroll
    for (int j = 0; j < 8; j++) {
        const float4* rp = (const float4*)(w1 + j * 12);
        ull c0, c1, c2, c3; ld4u(rp, c0, c1); ld4u(rp + 1, c2, c3);
        float bb = b1[j];
#pragma unroll
        for (int si = 0; si < NS; si++) {
            ull m = ffma2u(c0, h1p[si][0], 0ull);
            m = ffma2u(c1, h1p[si][1], m);
            m = ffma2u(c2, h1p[si][2], m);
            m = ffma2u(c3, h1p[si][3], m);
            g[si][j] = tanhfast(bb + redu(m));
        }
    }
    ull h2p[NS][4];
#pragma unroll
    for (int si = 0; si < NS; si++)
#pragma unroll
        for (int p = 0; p < 4; p++) h2p[si][p] = f2u(g[si][2 * p], g[si][2 * p + 1]);

    // L2: own 16 rows (contiguous half), processed in pairs
#pragma unroll
    for (int q = 0; q < 8; q++) {
        const int i0 = jh * 16 + 2 * q;
        const float* r0 = w2 + i0 * 8 + jh * 4;
        ull c0, c1, c2, c3, d0, d1, d2, d3;
        ld4u((const float4*)r0, c0, c1); ld4u((const float4*)r0 + 1, c2, c3);
        ld4u((const float4*)(r0 + 8), d0, d1); ld4u((const float4*)(r0 + 8) + 1, d2, d3);
        float bb0 = b2[i0], bb1 = b2[i0 + 1];
        ull pk[NS];
#pragma unroll
        for (int si = 0; si < NS; si++) {
            ull m0 = ffma2u(c0, h2p[si][0], 0ull);
            m0 = ffma2u(c1, h2p[si][1], m0);
            m0 = ffma2u(c2, h2p[si][2], m0);
            m0 = ffma2u(c3, h2p[si][3], m0);
            ull m1 = ffma2u(d0, h2p[si][0], 0ull);
            m1 = ffma2u(d1, h2p[si][1], m1);
            m1 = ffma2u(d2, h2p[si][2], m1);
            m1 = ffma2u(d3, h2p[si][3], m1);
            float v0 = bb0 + redu(m0), v1 = bb1 + redu(m1);
            if (role) { v0 = __expf(v0); v1 = __expf(v1); }
            pk[si] = f2u(v0, v1);
        }
#pragma unroll
        for (int si = 0; si < NS; si++) {
            ull ot = shflxu(pk[si], 2);        // role partner, same jh
            float w0_, w1_, o0, o1;
            u2ff(pk[si], w0_, w1_); u2ff(ot, o0, o1);
            float t0 = role ? o0 : w0_, e0 = role ? w0_ : o0;
            float t1 = role ? o1 : w1_, e1 = role ? w1_ : o1;
            float vx, vy; u2ff(v[si][q], vx, vy);
            v[si][q] = f2u(fmaf(vx, e0, t0), fmaf(vy, e1, t1));
        }
    }
}

// ---------------- backward phase ------------------------------------------
//   u_new = (u - t(a)) * exp(-s(a));  yu = (yu - (J_t + diag(u-t) J_s) yd) * exp(-s)
__device__ __forceinline__ void bwd_phase(const float* __restrict__ sm, int ibT,
                                          const ull (&a)[NS][8], ull (&u)[NS][8],
                                          float* __restrict__ ys0,
                                          int ydoff, int yuoff,
                                          int role, int jh) {
    const int ib = ibT + role;
    const float* w0 = sm + OFF_W0 + ib * W0_STR + jh * 20;
    const float* w1 = sm + OFF_W1 + ib * W1_STR;
    const float* w2 = sm + OFF_W2 + ib * W2_STR;
    const float* b0 = sm + OFF_B0 + ib * 8;
    const float* b1 = sm + OFF_B1 + ib * 8;
    const float* b2 = sm + OFF_B2 + ib * B2_STR;

    // fused L0: hidden (a) + JVP (d) partial dots; samples in pairs to cap regs
    float preH[NS][8], preD[NS][8];
#pragma unroll
    for (int sb = 0; sb < NS / 2; sb++) {
        ull dA[2][8];
#pragma unroll
        for (int s2 = 0; s2 < 2; s2++) {
            const float4* dv = (const float4*)(ys0 + (2 * sb + s2) * Y_SI + ydoff + jh * 16);
            ld4u(dv,     dA[s2][0], dA[s2][1]);
            ld4u(dv + 1, dA[s2][2], dA[s2][3]);
            ld4u(dv + 2, dA[s2][4], dA[s2][5]);
            ld4u(dv + 3, dA[s2][6], dA[s2][7]);
        }
#pragma unroll
        for (int j = 0; j < 8; j++) {
            const float4* rp = (const float4*)(w0 + j * 36);
            ull c[8];
            ld4u(rp, c[0], c[1]); ld4u(rp + 1, c[2], c[3]);
            ld4u(rp + 2, c[4], c[5]); ld4u(rp + 3, c[6], c[7]);
#pragma unroll
            for (int s2 = 0; s2 < 2; s2++) {
                const int si = 2 * sb + s2;
                ull mH = 0ull, mD = 0ull;
#pragma unroll
                for (int p = 0; p < 8; p++) {
                    mH = ffma2u(c[p], a[si][p], mH);
                    mD = ffma2u(c[p], dA[s2][p], mD);
                }
                preH[si][j] = redu(mH); preD[si][j] = redu(mD);
            }
        }
    }
    ull hO[NS][4], pO[NS][4];
#pragma unroll
    for (int si = 0; si < NS; si++) {
        ull hA = f2u(preH[si][0], preH[si][1]), hB = f2u(preH[si][2], preH[si][3]);
        ull hC = f2u(preH[si][4], preH[si][5]), hD = f2u(preH[si][6], preH[si][7]);
        ull dA_ = f2u(preD[si][0], preD[si][1]), dB = f2u(preD[si][2], preD[si][3]);
        ull dC = f2u(preD[si][4], preD[si][5]), dD = f2u(preD[si][6], preD[si][7]);
        hA = addx2(hA, shflxu(hA, 1)); hB = addx2(hB, shflxu(hB, 1));
        hC = addx2(hC, shflxu(hC, 1)); hD = addx2(hD, shflxu(hD, 1));
        dA_ = addx2(dA_, shflxu(dA_, 1)); dB = addx2(dB, shflxu(dB, 1));
        dC = addx2(dC, shflxu(dC, 1)); dD = addx2(dD, shflxu(dD, 1));
        float s[8], e[8];
        u2ff(hA, s[0], s[1]); u2ff(hB, s[2], s[3]); u2ff(hC, s[4], s[5]); u2ff(hD, s[6], s[7]);
        u2ff(dA_, e[0], e[1]); u2ff(dB, e[2], e[3]); u2ff(dC, e[4], e[5]); u2ff(dD, e[6], e[7]);
        float hv[8], pv[8];
#pragma unroll
        for (int j = 0; j < 8; j++) {
            float t = tanhfast(b0[j] + s[j]);
            hv[j] = t; pv[j] = (1.f - t * t) * e[j];
        }
#pragma unroll
        for (int p = 0; p < 4; p++) {
            hO[si][p] = f2u(hv[2 * p], hv[2 * p + 1]);
            pO[si][p] = f2u(pv[2 * p], pv[2 * p + 1]);
        }
    }

    // fused L1: fully local
    float gH[NS][8], gQ[NS][8];
#pragma unroll
    for (int j = 0; j < 8; j++) {
        const float4* rp = (const float4*)(w1 + j * 12);
        ull c0, c1, c2, c3; ld4u(rp, c0, c1); ld4u(rp + 1, c2, c3);
        float bb = b1[j];
#pragma unroll
        for (int si = 0; si < NS; si++) {
            ull mH = ffma2u(c0, hO[si][0], 0ull); mH = ffma2u(c1, hO[si][1], mH);
            mH = ffma2u(c2, hO[si][2], mH); mH = ffma2u(c3, hO[si][3], mH);
            ull mQ = ffma2u(c0, pO[si][0], 0ull); mQ = ffma2u(c1, pO[si][1], mQ);
            mQ = ffma2u(c2, pO[si][2], mQ); mQ = ffma2u(c3, pO[si][3], mQ);
            float t = tanhfast(bb + redu(mH));
            gH[si][j] = t; gQ[si][j] = (1.f - t * t) * redu(mQ);
        }
    }
    ull h2p[NS][4], qp[NS][4];
#pragma unroll
    for (int si = 0; si < NS; si++)
#pragma unroll
        for (int p = 0; p < 4; p++) {
            h2p[si][p] = f2u(gH[si][2 * p], gH[si][2 * p + 1]);
            qp[si][p]  = f2u(gQ[si][2 * p], gQ[si][2 * p + 1]);
        }

    // L2: own 16 rows in pairs; role-exch ^2; inverse update in place
#pragma unroll
    for (int q = 0; q < 8; q++) {
        const int i0 = jh * 16 + 2 * q;
        const float* r0 = w2 + i0 * 8 + jh * 4;
        ull c0, c1, c2, c3, d0, d1, d2, d3;
        ld4u((const float4*)r0, c0, c1); ld4u((const float4*)r0 + 1, c2, c3);
        ld4u((const float4*)(r0 + 8), d0, d1); ld4u((const float4*)(r0 + 8) + 1, d2, d3);
        float bb0 = b2[i0], bb1 = b2[i0 + 1];
        ull pkR[NS], pkX[NS];
#pragma unroll
        for (int si = 0; si < NS; si++) {
            ull m0 = ffma2u(c0, h2p[si][0], 0ull);
            m0 = ffma2u(c1, h2p[si][1], m0);
            m0 = ffma2u(c2, h2p[si][2], m0);
            m0 = ffma2u(c3, h2p[si][3], m0);
            ull m1 = ffma2u(d0, h2p[si][0], 0ull);
            m1 = ffma2u(d1, h2p[si][1], m1);
            m1 = ffma2u(d2, h2p[si][2], m1);
            m1 = ffma2u(d3, h2p[si][3], m1);
            ull x0 = ffma2u(c0, qp[si][0], 0ull);
            x0 = ffma2u(c1, qp[si][1], x0);
            x0 = ffma2u(c2, qp[si][2], x0);
            x0 = ffma2u(c3, qp[si][3], x0);
            ull x1 = ffma2u(d0, qp[si][0], 0ull);
            x1 = ffma2u(d1, qp[si][1], x1);
            x1 = ffma2u(d2, qp[si][2], x1);
            x1 = ffma2u(d3, qp[si][3], x1);
            float r0v = bb0 + redu(m0), r1v = bb1 + redu(m1);
            if (role) { r0v = __expf(-r0v); r1v = __expf(-r1v); }  // S sends e^{-s}
            pkR[si] = f2u(r0v, r1v);
            pkX[si] = f2u(redu(x0), redu(x1));
        }
#pragma unroll
        for (int si = 0; si < NS; si++) {
            ull oR = shflxu(pkR[si], 2);
            ull oX = shflxu(pkX[si], 2);
            float a0, a1, b0_, b1_, c0_, c1_, d0_, d1_;
            u2ff(pkR[si], a0, a1); u2ff(oR, b0_, b1_);
            u2ff(pkX[si], c0_, c1_); u2ff(oX, d0_, d1_);
            float tt0 = role ? b0_ : a0, ee0 = role ? a0 : b0_;
            float tt1 = role ? b1_ : a1, ee1 = role ? a1 : b1_;
            float cT0 = role ? d0_ : c0_, dS0 = role ? c0_ : d0_;
            float cT1 = role ? d1_ : c1_, dS1 = role ? c1_ : d1_;
            float ux, uy; u2ff(u[si][q], ux, uy);
            float dd0 = ux - tt0, dd1 = uy - tt1;      // = u_prev * e^{s}
            u[si][q] = f2u(dd0 * ee0, dd1 * ee1);
            if (!role) {
                float cv0 = cT0 + dd0 * dS0;
                float cv1 = cT1 + dd1 * dS1;
                float2* yp = (float2*)(ys0 + si * Y_SI + yuoff + i0);
                float2 old = *yp;
                *yp = make_float2((old.x - cv0) * ee0, (old.y - cv1) * ee1);
            }
        }
    }
}

__global__ __launch_bounds__(TPB, 1)
void nf10_kernel(const float* __restrict__ gX, const float* __restrict__ gXs,
                 const float* __restrict__ gW0, const float* __restrict__ gB0,
                 const float* __restrict__ gW1, const float* __restrict__ gB1,
                 const float* __restrict__ gW2, const float* __restrict__ gB2,
                 float* __restrict__ gOut) {
    extern __shared__ float sm[];
    const int tid = threadIdx.x;

    // cooperative weight load, skewed layouts
    for (int i = tid; i < 8192; i += TPB) {           // W0: 16|pad4|16 rows of 36
        int ib = i >> 8, j = (i >> 5) & 7, c = i & 31;
        sm[OFF_W0 + ib * W0_STR + j * 36 + c + (c >> 4) * 4] = gW0[i];
    }
    for (int i = tid; i < 2048; i += TPB) {           // W1: rows of 12
        int ib = i >> 6, j = (i >> 3) & 7, c = i & 7;
        sm[OFF_W1 + ib * W1_STR + j * 12 + c] = gW1[i];
    }
    for (int i = tid; i < 8192; i += TPB) {           // W2: +4 skew for rows>=16
        int ib = i >> 8, row = (i >> 3) & 31, c = i & 7;
        sm[OFF_W2 + ib * W2_STR + row * 8 + (row >> 4) * 4 + c] = gW2[i];
    }
    for (int i = tid; i < 256;  i += TPB) sm[OFF_B0 + i] = gB0[i];
    for (int i = tid; i < 256;  i += TPB) sm[OFF_B1 + i] = gB1[i];
    for (int i = tid; i < 1024; i += TPB) sm[OFF_B2 + (i >> 5) * B2_STR + (i & 31)] = gB2[i];
    __syncthreads();

    const int jh   = tid & 1;
    const int role = (tid >> 1) & 1;
    const int quad = tid & 3;
    const int slot = tid >> 2;                  // 0..31
    const int s0   = blockIdx.x * SPB + slot;   // samples s0 + si*SLOTS

    // distributed state: own jh-half (16 floats) of lo/up, 4 samples
    ull lo[NS][8], up[NS][8];
#pragma unroll
    for (int si = 0; si < NS; si++) {
        const float* base = gX + (size_t)(s0 + si * SLOTS) * 64;
        const float4* pl = (const float4*)(base + jh * 16);
        const float4* pu = (const float4*)(base + 32 + jh * 16);
#pragma unroll
        for (int qq = 0; qq < 4; qq++) {
            ld4u(pl + qq, lo[si][2 * qq], lo[si][2 * qq + 1]);
            ld4u(pu + qq, up[si][2 * qq], up[si][2 * qq + 1]);
        }
    }

    // ---------- forward: z = phi(x) ----------
    for (int k = 0; k < NF; k++) {
        fwd_phase(sm, k * 4 + 0, lo, up, role, jh);   // up' = t1(lo)+up*exp(s1(lo))
        fwd_phase(sm, k * 4 + 2, up, lo, role, jh);   // lo' = t2(up')+lo*exp(s2(up'))
    }

    // ---------- rhs: g = -2 (x - x_star); each lane writes 16 of 64 ----------
    float* ys0 = sm + OFF_Y + slot * Y_STRIDE;
#pragma unroll
    for (int si = 0; si < NS; si++) {
        const int samp = s0 + si * SLOTS;
        const float4* xp = (const float4*)(gX  + (size_t)samp * 64 + quad * 16);
        const float4* sp = (const float4*)(gXs + (size_t)samp * 64 + quad * 16);
        float4* yh = (float4*)(ys0 + si * Y_SI + quad * 16);
#pragma unroll
        for (int t = 0; t < 4; t++) {
            float4 xa = xp[t], xb = sp[t];
            yh[t] = make_float4(-2.f * (xa.x - xb.x), -2.f * (xa.y - xb.y),
                                -2.f * (xa.z - xb.z), -2.f * (xa.w - xb.w));
        }
    }
    __syncwarp();

    // ---------- backward: y <- J_k^{-1} y with exact state reconstruction ----
    for (int k = NF - 1; k >= 0; k--) {
        bwd_phase(sm, k * 4 + 2, up, lo, ys0, 32, 0, role, jh);   // invert lo-update
        __syncwarp();
        bwd_phase(sm, k * 4 + 0, lo, up, ys0, 0, 32, role, jh);   // invert up-update
        __syncwarp();
    }

    // ---------- output: each lane writes 16 of 64 per sample ----------
#pragma unroll
    for (int si = 0; si < NS; si++) {
        const int samp = s0 + si * SLOTS;
        float4* op = (float4*)(gOut + (size_t)samp * 64 + quad * 16);
        const float4* yh = (const float4*)(ys0 + si * Y_SI + quad * 16);
#pragma unroll
        for (int t = 0; t < 4; t++) op[t] = yh[t];
    }
}

extern "C" void kernel_launch(void* const* d_in, const int* in_sizes, int n_in,
                              void* d_out, int out_size) {
    const float* x  = (const float*)d_in[0];
    const float* xs = (const float*)d_in[1];
    const float* W0 = (const float*)d_in[2];
    const float* b0 = (const float*)d_in[3];
    const float* W1 = (const float*)d_in[4];
    const float* b1 = (const float*)d_in[5];
    const float* W2 = (const float*)d_in[6];
    const float* b2 = (const float*)d_in[7];
    float* out = (float*)d_out;

    cudaFuncSetAttribute(nf10_kernel, cudaFuncAttributeMaxDynamicSharedMemorySize, SMEM_BYTES);
    nf10_kernel<<<BSZ / SPB, TPB, SMEM_BYTES>>>(x, xs, W0, b0, W1, b1, W2, b2, out);
}

// round 16
// speedup vs baseline: 1.7685x; 1.7685x over previous
#include <cuda_runtime.h>
#include <cuda_bf16.h>

typedef unsigned long long ull;

#define BSZ   16384
#define NF    8
#define TPB   256          // 64 slots × 4 lanes; 2 samples/thread
#define SLOTS 64
#define NS    2
#define SPB   (SLOTS * NS) // 128 samples per block

#define W0_STR 296         // per-net: 8 rows × 36 (16|pad4|16)
#define W1_STR 104         // 8 rows × 12 (8|pad4)
#define W2_STR 272         // 32 rows × 8, +4 skew for rows>=16
#define B2_STR 36

#define OFF_W0 0           // 32*296 = 9472
#define OFF_W1 9472        // 32*104 = 3328
#define OFF_W2 12800       // 32*272 = 8704
#define OFF_B0 21504
#define OFF_B1 21760
#define OFF_B2 22016       // 32*36 = 1152
#define OFF_Y  23168
#define Y_STRIDE 68
#define Y_SI   (SLOTS * Y_STRIDE)
#define SMEM_FLOATS (OFF_Y + SPB * Y_STRIDE)
#define SMEM_BYTES  (SMEM_FLOATS * 4)

__device__ __forceinline__ ull ffma2u(ull a, ull b, ull c) {
    asm("fma.rn.f32x2 %0, %1, %2, %0;" : "+l"(c) : "l"(a), "l"(b));
    return c;
}
__device__ __forceinline__ ull addx2(ull a, ull b) {
    ull r; asm("add.rn.f32x2 %0, %1, %2;" : "=l"(r) : "l"(a), "l"(b));
    return r;
}
__device__ __forceinline__ ull f2u(float x, float y) {
    ull u; asm("mov.b64 %0, {%1, %2};" : "=l"(u) : "f"(x), "f"(y)); return u;
}
__device__ __forceinline__ void u2ff(ull u, float& x, float& y) {
    asm("mov.b64 {%0, %1}, %2;" : "=f"(x), "=f"(y) : "l"(u));
}
__device__ __forceinline__ void ld4u(const float4* p, ull& u0, ull& u1) {
    float4 v = *p; u0 = f2u(v.x, v.y); u1 = f2u(v.z, v.w);
}
__device__ __forceinline__ float redu(ull u) {
    float x, y; u2ff(u, x, y); return x + y;
}
__device__ __forceinline__ float tanhfast(float x) {
    float r; asm("tanh.approx.f32 %0, %1;" : "=f"(r) : "f"(x));
    return r;
}
__device__ __forceinline__ ull shflxu(ull v, int m) {
    return __shfl_xor_sync(0xFFFFFFFFu, v, m);
}

// ---------------- forward phase -------------------------------------------
// Lane (role, jh): role 0 = t-net, 1 = s-net. State distributed by jh
// (own positions [jh*16, +16) of each vector), replicated across role.
// L0: all 8 rows, partial dot over own 16 inputs, reduce ^1 -> full h1 local.
// L1: all 8 rows, fully local (no exchange). L2: own 16 rows, role-exch ^2.
__device__ __forceinline__ void fwd_phase(const float* __restrict__ sm, int ibT,
                                          const ull (&a)[NS][8], ull (&v)[NS][8],
                                          int role, int jh) {
    const int ib = ibT + role;
    const float* w0 = sm + OFF_W0 + ib * W0_STR + jh * 20;
    const float* w1 = sm + OFF_W1 + ib * W1_STR;
    const float* w2 = sm + OFF_W2 + ib * W2_STR;
    const float* b0 = sm + OFF_B0 + ib * 8;
    const float* b1 = sm + OFF_B1 + ib * 8;
    const float* b2 = sm + OFF_B2 + ib * B2_STR;

    // L0 partial dots
    float pre[NS][8];
#pragma unroll
    for (int j = 0; j < 8; j++) {
        const float4* rp = (const float4*)(w0 + j * 36);
        ull c[8];
        ld4u(rp, c[0], c[1]); ld4u(rp + 1, c[2], c[3]);
        ld4u(rp + 2, c[4], c[5]); ld4u(rp + 3, c[6], c[7]);
#pragma unroll
        for (int si = 0; si < NS; si++) {
            ull m = 0ull;
#pragma unroll
            for (int p = 0; p < 8; p++) m = ffma2u(c[p], a[si][p], m);
            pre[si][j] = redu(m);
        }
    }
    ull h1p[NS][4];
#pragma unroll
    for (int si = 0; si < NS; si++) {
        ull pA = f2u(pre[si][0], pre[si][1]), pB = f2u(pre[si][2], pre[si][3]);
        ull pC = f2u(pre[si][4], pre[si][5]), pD = f2u(pre[si][6], pre[si][7]);
        pA = addx2(pA, shflxu(pA, 1)); pB = addx2(pB, shflxu(pB, 1));
        pC = addx2(pC, shflxu(pC, 1)); pD = addx2(pD, shflxu(pD, 1));
        float s0, s1, s2, s3, s4, s5, s6, s7;
        u2ff(pA, s0, s1); u2ff(pB, s2, s3); u2ff(pC, s4, s5); u2ff(pD, s6, s7);
        h1p[si][0] = f2u(tanhfast(b0[0] + s0), tanhfast(b0[1] + s1));
        h1p[si][1] = f2u(tanhfast(b0[2] + s2), tanhfast(b0[3] + s3));
        h1p[si][2] = f2u(tanhfast(b0[4] + s4), tanhfast(b0[5] + s5));
        h1p[si][3] = f2u(tanhfast(b0[6] + s6), tanhfast(b0[7] + s7));
    }

    // L1 fully local
    float g[NS][8];
#pragma unroll
    for (int j = 0; j < 8; j++) {
        const float4* rp = (const float4*)(w1 + j * 12);
        ull c0, c1, c2, c3; ld4u(rp, c0, c1); ld4u(rp + 1, c2, c3);
        float bb = b1[j];
#pragma unroll
        for (int si = 0; si < NS; si++) {
            ull m = ffma2u(c0, h1p[si][0], 0ull);
            m = ffma2u(c1, h1p[si][1], m);
            m = ffma2u(c2, h1p[si][2], m);
            m = ffma2u(c3, h1p[si][3], m);
            g[si][j] = tanhfast(bb + redu(m));
        }
    }
    ull h2p[NS][4];
#pragma unroll
    for (int si = 0; si < NS; si++)
#pragma unroll
        for (int p = 0; p < 4; p++) h2p[si][p] = f2u(g[si][2 * p], g[si][2 * p + 1]);

    // L2: own 16 rows (contiguous half), processed in pairs
#pragma unroll
    for (int q = 0; q < 8; q++) {
        const int i0 = jh * 16 + 2 * q;
        const float* r0 = w2 + i0 * 8 + jh * 4;
        ull c0, c1, c2, c3, d0, d1, d2, d3;
        ld4u((const float4*)r0, c0, c1); ld4u((const float4*)r0 + 1, c2, c3);
        ld4u((const float4*)(r0 + 8), d0, d1); ld4u((const float4*)(r0 + 8) + 1, d2, d3);
        float bb0 = b2[i0], bb1 = b2[i0 + 1];
        ull pk[NS];
#pragma unroll
        for (int si = 0; si < NS; si++) {
            ull m0 = ffma2u(c0, h2p[si][0], 0ull);
            m0 = ffma2u(c1, h2p[si][1], m0);
            m0 = ffma2u(c2, h2p[si][2], m0);
            m0 = ffma2u(c3, h2p[si][3], m0);
            ull m1 = ffma2u(d0, h2p[si][0], 0ull);
            m1 = ffma2u(d1, h2p[si][1], m1);
            m1 = ffma2u(d2, h2p[si][2], m1);
            m1 = ffma2u(d3, h2p[si][3], m1);
            float v0 = bb0 + redu(m0), v1 = bb1 + redu(m1);
            if (role) { v0 = __expf(v0); v1 = __expf(v1); }
            pk[si] = f2u(v0, v1);
        }
#pragma unroll
        for (int si = 0; si < NS; si++) {
            ull ot = shflxu(pk[si], 2);        // role partner, same jh
            float w0_, w1_, o0, o1;
            u2ff(pk[si], w0_, w1_); u2ff(ot, o0, o1);
            float t0 = role ? o0 : w0_, e0 = role ? w0_ : o0;
            float t1 = role ? o1 : w1_, e1 = role ? w1_ : o1;
            float vx, vy; u2ff(v[si][q], vx, vy);
            v[si][q] = f2u(fmaf(vx, e0, t0), fmaf(vy, e1, t1));
        }
    }
}

// ---------------- backward phase ------------------------------------------
//   u_new = (u - t(a)) * exp(-s(a));  yu = (yu - (J_t + diag(u-t) J_s) yd) * exp(-s)
__device__ __forceinline__ void bwd_phase(const float* __restrict__ sm, int ibT,
                                          const ull (&a)[NS][8], ull (&u)[NS][8],
                                          float* __restrict__ ys0,
                                          int ydoff, int yuoff,
                                          int role, int jh) {
    const int ib = ibT + role;
    const float* w0 = sm + OFF_W0 + ib * W0_STR + jh * 20;
    const float* w1 = sm + OFF_W1 + ib * W1_STR;
    const float* w2 = sm + OFF_W2 + ib * W2_STR;
    const float* b0 = sm + OFF_B0 + ib * 8;
    const float* b1 = sm + OFF_B1 + ib * 8;
    const float* b2 = sm + OFF_B2 + ib * B2_STR;

    // fused L0: hidden (a) + JVP (d) partial dots
    float preH[NS][8], preD[NS][8];
    {
        ull dA[NS][8];
#pragma unroll
        for (int si = 0; si < NS; si++) {
            const float4* dv = (const float4*)(ys0 + si * Y_SI + ydoff + jh * 16);
            ld4u(dv,     dA[si][0], dA[si][1]);
            ld4u(dv + 1, dA[si][2], dA[si][3]);
            ld4u(dv + 2, dA[si][4], dA[si][5]);
            ld4u(dv + 3, dA[si][6], dA[si][7]);
        }
#pragma unroll
        for (int j = 0; j < 8; j++) {
            const float4* rp = (const float4*)(w0 + j * 36);
            ull c[8];
            ld4u(rp, c[0], c[1]); ld4u(rp + 1, c[2], c[3]);
            ld4u(rp + 2, c[4], c[5]); ld4u(rp + 3, c[6], c[7]);
#pragma unroll
            for (int si = 0; si < NS; si++) {
                ull mH = 0ull, mD = 0ull;
#pragma unroll
                for (int p = 0; p < 8; p++) {
                    mH = ffma2u(c[p], a[si][p], mH);
                    mD = ffma2u(c[p], dA[si][p], mD);
                }
                preH[si][j] = redu(mH); preD[si][j] = redu(mD);
            }
        }
    }
    ull hO[NS][4], pO[NS][4];
#pragma unroll
    for (int si = 0; si < NS; si++) {
        ull hA = f2u(preH[si][0], preH[si][1]), hB = f2u(preH[si][2], preH[si][3]);
        ull hC = f2u(preH[si][4], preH[si][5]), hD = f2u(preH[si][6], preH[si][7]);
        ull dA_ = f2u(preD[si][0], preD[si][1]), dB = f2u(preD[si][2], preD[si][3]);
        ull dC = f2u(preD[si][4], preD[si][5]), dD = f2u(preD[si][6], preD[si][7]);
        hA = addx2(hA, shflxu(hA, 1)); hB = addx2(hB, shflxu(hB, 1));
        hC = addx2(hC, shflxu(hC, 1)); hD = addx2(hD, shflxu(hD, 1));
        dA_ = addx2(dA_, shflxu(dA_, 1)); dB = addx2(dB, shflxu(dB, 1));
        dC = addx2(dC, shflxu(dC, 1)); dD = addx2(dD, shflxu(dD, 1));
        float s[8], e[8];
        u2ff(hA, s[0], s[1]); u2ff(hB, s[2], s[3]); u2ff(hC, s[4], s[5]); u2ff(hD, s[6], s[7]);
        u2ff(dA_, e[0], e[1]); u2ff(dB, e[2], e[3]); u2ff(dC, e[4], e[5]); u2ff(dD, e[6], e[7]);
        float hv[8], pv[8];
#pragma unroll
        for (int j = 0; j < 8; j++) {
            float t = tanhfast(b0[j] + s[j]);
            hv[j] = t; pv[j] = (1.f - t * t) * e[j];
        }
#pragma unroll
        for (int p = 0; p < 4; p++) {
            hO[si][p] = f2u(hv[2 * p], hv[2 * p + 1]);
            pO[si][p] = f2u(pv[2 * p], pv[2 * p + 1]);
        }
    }

    // fused L1: fully local
    float gH[NS][8], gQ[NS][8];
#pragma unroll
    for (int j = 0; j < 8; j++) {
        const float4* rp = (const float4*)(w1 + j * 12);
        ull c0, c1, c2, c3; ld4u(rp, c0, c1); ld4u(rp + 1, c2, c3);
        float bb = b1[j];
#pragma unroll
        for (int si = 0; si < NS; si++) {
            ull mH = ffma2u(c0, hO[si][0], 0ull); mH = ffma2u(c1, hO[si][1], mH);
            mH = ffma2u(c2, hO[si][2], mH); mH = ffma2u(c3, hO[si][3], mH);
            ull mQ = ffma2u(c0, pO[si][0], 0ull); mQ = ffma2u(c1, pO[si][1], mQ);
            mQ = ffma2u(c2, pO[si][2], mQ); mQ = ffma2u(c3, pO[si][3], mQ);
            float t = tanhfast(bb + redu(mH));
            gH[si][j] = t; gQ[si][j] = (1.f - t * t) * redu(mQ);
        }
    }
    ull h2p[NS][4], qp[NS][4];
#pragma unroll
    for (int si = 0; si < NS; si++)
#pragma unroll
        for (int p = 0; p < 4; p++) {
            h2p[si][p] = f2u(gH[si][2 * p], gH[si][2 * p + 1]);
            qp[si][p]  = f2u(gQ[si][2 * p], gQ[si][2 * p + 1]);
        }

    // L2: own 16 rows in pairs; role-exch ^2; inverse update in place
#pragma unroll
    for (int q = 0; q < 8; q++) {
        const int i0 = jh * 16 + 2 * q;
        const float* r0 = w2 + i0 * 8 + jh * 4;
        ull c0, c1, c2, c3, d0, d1, d2, d3;
        ld4u((const float4*)r0, c0, c1); ld4u((const float4*)r0 + 1, c2, c3);
        ld4u((const float4*)(r0 + 8), d0, d1); ld4u((const float4*)(r0 + 8) + 1, d2, d3);
        float bb0 = b2[i0], bb1 = b2[i0 + 1];
        ull pkR[NS], pkX[NS];
#pragma unroll
        for (int si = 0; si < NS; si++) {
            ull m0 = ffma2u(c0, h2p[si][0], 0ull);
            m0 = ffma2u(c1, h2p[si][1], m0);
            m0 = ffma2u(c2, h2p[si][2], m0);
            m0 = ffma2u(c3, h2p[si][3], m0);
            ull m1 = ffma2u(d0, h2p[si][0], 0ull);
            m1 = ffma2u(d1, h2p[si][1], m1);
            m1 = ffma2u(d2, h2p[si][2], m1);
            m1 = ffma2u(d3, h2p[si][3], m1);
            ull x0 = ffma2u(c0, qp[si][0], 0ull);
            x0 = ffma2u(c1, qp[si][1], x0);
            x0 = ffma2u(c2, qp[si][2], x0);
            x0 = ffma2u(c3, qp[si][3], x0);
            ull x1 = ffma2u(d0, qp[si][0], 0ull);
            x1 = ffma2u(d1, qp[si][1], x1);
            x1 = ffma2u(d2, qp[si][2], x1);
            x1 = ffma2u(d3, qp[si][3], x1);
            float r0v = bb0 + redu(m0), r1v = bb1 + redu(m1);
            if (role) { r0v = __expf(-r0v); r1v = __expf(-r1v); }  // S sends e^{-s}
            pkR[si] = f2u(r0v, r1v);
            pkX[si] = f2u(redu(x0), redu(x1));
        }
#pragma unroll
        for (int si = 0; si < NS; si++) {
            ull oR = shflxu(pkR[si], 2);
            ull oX = shflxu(pkX[si], 2);
            float a0, a1, b0_, b1_, c0_, c1_, d0_, d1_;
            u2ff(pkR[si], a0, a1); u2ff(oR, b0_, b1_);
            u2ff(pkX[si], c0_, c1_); u2ff(oX, d0_, d1_);
            float tt0 = role ? b0_ : a0, ee0 = role ? a0 : b0_;
            float tt1 = role ? b1_ : a1, ee1 = role ? a1 : b1_;
            float cT0 = role ? d0_ : c0_, dS0 = role ? c0_ : d0_;
            float cT1 = role ? d1_ : c1_, dS1 = role ? c1_ : d1_;
            float ux, uy; u2ff(u[si][q], ux, uy);
            float dd0 = ux - tt0, dd1 = uy - tt1;      // = u_prev * e^{s}
            u[si][q] = f2u(dd0 * ee0, dd1 * ee1);
            if (!role) {
                float cv0 = cT0 + dd0 * dS0;
                float cv1 = cT1 + dd1 * dS1;
                float2* yp = (float2*)(ys0 + si * Y_SI + yuoff + i0);
                float2 old = *yp;
                *yp = make_float2((old.x - cv0) * ee0, (old.y - cv1) * ee1);
            }
        }
    }
}

__global__ __launch_bounds__(TPB, 1)
void nf11_kernel(const float* __restrict__ gX, const float* __restrict__ gXs,
                 const float* __restrict__ gW0, const float* __restrict__ gB0,
                 const float* __restrict__ gW1, const float* __restrict__ gB1,
                 const float* __restrict__ gW2, const float* __restrict__ gB2,
                 float* __restrict__ gOut) {
    extern __shared__ float sm[];
    const int tid = threadIdx.x;

    // cooperative weight load, skewed layouts
    for (int i = tid; i < 8192; i += TPB) {           // W0: 16|pad4|16 rows of 36
        int ib = i >> 8, j = (i >> 5) & 7, c = i & 31;
        sm[OFF_W0 + ib * W0_STR + j * 36 + c + (c >> 4) * 4] = gW0[i];
    }
    for (int i = tid; i < 2048; i += TPB) {           // W1: rows of 12
        int ib = i >> 6, j = (i >> 3) & 7, c = i & 7;
        sm[OFF_W1 + ib * W1_STR + j * 12 + c] = gW1[i];
    }
    for (int i = tid; i < 8192; i += TPB) {           // W2: +4 skew for rows>=16
        int ib = i >> 8, row = (i >> 3) & 31, c = i & 7;
        sm[OFF_W2 + ib * W2_STR + row * 8 + (row >> 4) * 4 + c] = gW2[i];
    }
    for (int i = tid; i < 256;  i += TPB) sm[OFF_B0 + i] = gB0[i];
    for (int i = tid; i < 256;  i += TPB) sm[OFF_B1 + i] = gB1[i];
    for (int i = tid; i < 1024; i += TPB) sm[OFF_B2 + (i >> 5) * B2_STR + (i & 31)] = gB2[i];
    __syncthreads();

    const int jh   = tid & 1;
    const int role = (tid >> 1) & 1;
    const int quad = tid & 3;
    const int slot = tid >> 2;                  // 0..63
    const int s0   = blockIdx.x * SPB + slot;   // samples s0 + si*SLOTS

    // distributed state: own jh-half (16 floats) of lo/up, NS samples
    ull lo[NS][8], up[NS][8];
#pragma unroll
    for (int si = 0; si < NS; si++) {
        const float* base = gX + (size_t)(s0 + si * SLOTS) * 64;
        const float4* pl = (const float4*)(base + jh * 16);
        const float4* pu = (const float4*)(base + 32 + jh * 16);
#pragma unroll
        for (int qq = 0; qq < 4; qq++) {
            ld4u(pl + qq, lo[si][2 * qq], lo[si][2 * qq + 1]);
            ld4u(pu + qq, up[si][2 * qq], up[si][2 * qq + 1]);
        }
    }

    // ---------- forward: z = phi(x) ----------
    for (int k = 0; k < NF; k++) {
        fwd_phase(sm, k * 4 + 0, lo, up, role, jh);   // up' = t1(lo)+up*exp(s1(lo))
        fwd_phase(sm, k * 4 + 2, up, lo, role, jh);   // lo' = t2(up')+lo*exp(s2(up'))
    }

    // ---------- rhs: g = -2 (x - x_star); each lane writes 16 of 64 ----------
    float* ys0 = sm + OFF_Y + slot * Y_STRIDE;
#pragma unroll
    for (int si = 0; si < NS; si++) {
        const int samp = s0 + si * SLOTS;
        const float4* xp = (const float4*)(gX  + (size_t)samp * 64 + quad * 16);
        const float4* sp = (const float4*)(gXs + (size_t)samp * 64 + quad * 16);
        float4* yh = (float4*)(ys0 + si * Y_SI + quad * 16);
#pragma unroll
        for (int t = 0; t < 4; t++) {
            float4 xa = xp[t], xb = sp[t];
            yh[t] = make_float4(-2.f * (xa.x - xb.x), -2.f * (xa.y - xb.y),
                                -2.f * (xa.z - xb.z), -2.f * (xa.w - xb.w));
        }
    }
    __syncwarp();

    // ---------- backward: y <- J_k^{-1} y with exact state reconstruction ----
    for (int k = NF - 1; k >= 0; k--) {
        bwd_phase(sm, k * 4 + 2, up, lo, ys0, 32, 0, role, jh);   // invert lo-update
        __syncwarp();
        bwd_phase(sm, k * 4 + 0, lo, up, ys0, 0, 32, role, jh);   // invert up-update
        __syncwarp();
    }

    // ---------- output: each lane writes 16 of 64 per sample ----------
#pragma unroll
    for (int si = 0; si < NS; si++) {
        const int samp = s0 + si * SLOTS;
        float4* op = (float4*)(gOut + (size_t)samp * 64 + quad * 16);
        const float4* yh = (const float4*)(ys0 + si * Y_SI + quad * 16);
#pragma unroll
        for (int t = 0; t < 4; t++) op[t] = yh[t];
    }
}

extern "C" void kernel_launch(void* const* d_in, const int* in_sizes, int n_in,
                              void* d_out, int out_size) {
    const float* x  = (const float*)d_in[0];
    const float* xs = (const float*)d_in[1];
    const float* W0 = (const float*)d_in[2];
    const float* b0 = (const float*)d_in[3];
    const float* W1 = (const float*)d_in[4];
    const float* b1 = (const float*)d_in[5];
    const float* W2 = (const float*)d_in[6];
    const float* b2 = (const float*)d_in[7];
    float* out = (float*)d_out;

    cudaFuncSetAttribute(nf11_kernel, cudaFuncAttributeMaxDynamicSharedMemorySize, SMEM_BYTES);
    nf11_kernel<<<BSZ / SPB, TPB, SMEM_BYTES>>>(x, xs, W0, b0, W1, b1, W2, b2, out);
}

// round 17
// speedup vs baseline: 1.8169x; 1.0274x over previous
#include <cuda_runtime.h>
#include <cuda_bf16.h>

typedef unsigned long long ull;

#define BSZ   16384
#define NF    8
#define TPB   256          // 64 slots × 4 lanes; 2 samples/thread
#define SLOTS 64
#define NS    2
#define SPB   (SLOTS * NS) // 128 samples per block

#define W0_STR 296         // per-net: 8 rows × 36 (16|pad4|16)
#define W1_STR 104         // 8 rows × 12 (8|pad4)
#define W2_STR 272         // 32 rows × 8, +4 skew for rows>=16
#define B2_STR 36

#define OFF_W0 0           // 32*296 = 9472
#define OFF_W1 9472        // 32*104 = 3328
#define OFF_W2 12800       // 32*272 = 8704
#define OFF_B0 21504
#define OFF_B1 21760
#define OFF_B2 22016       // 32*36 = 1152
#define SMEM_FLOATS 23168  // 92.7 KB — no Y buffer anymore
#define SMEM_BYTES  (SMEM_FLOATS * 4)

__device__ __forceinline__ ull ffma2u(ull a, ull b, ull c) {
    asm("fma.rn.f32x2 %0, %1, %2, %0;" : "+l"(c) : "l"(a), "l"(b));
    return c;
}
__device__ __forceinline__ ull addx2(ull a, ull b) {
    ull r; asm("add.rn.f32x2 %0, %1, %2;" : "=l"(r) : "l"(a), "l"(b));
    return r;
}
__device__ __forceinline__ ull f2u(float x, float y) {
    ull u; asm("mov.b64 %0, {%1, %2};" : "=l"(u) : "f"(x), "f"(y)); return u;
}
__device__ __forceinline__ void u2ff(ull u, float& x, float& y) {
    asm("mov.b64 {%0, %1}, %2;" : "=f"(x), "=f"(y) : "l"(u));
}
__device__ __forceinline__ void ld4u(const float4* p, ull& u0, ull& u1) {
    float4 v = *p; u0 = f2u(v.x, v.y); u1 = f2u(v.z, v.w);
}
__device__ __forceinline__ float redu(ull u) {
    float x, y; u2ff(u, x, y); return x + y;
}
__device__ __forceinline__ float tanhfast(float x) {
    float r; asm("tanh.approx.f32 %0, %1;" : "=f"(r) : "f"(x));
    return r;
}
__device__ __forceinline__ ull shflxu(ull v, int m) {
    return __shfl_xor_sync(0xFFFFFFFFu, v, m);
}

// ---------------- forward phase -------------------------------------------
// Lane (role, jh): role 0 = t-net, 1 = s-net. State distributed by jh
// (own positions [jh*16, +16)), replicated across role.
__device__ __forceinline__ void fwd_phase(const float* __restrict__ sm, int ibT,
                                          const ull (&a)[NS][8], ull (&v)[NS][8],
                                          int role, int jh) {
    const int ib = ibT + role;
    const float* w0 = sm + OFF_W0 + ib * W0_STR + jh * 20;
    const float* w1 = sm + OFF_W1 + ib * W1_STR;
    const float* w2 = sm + OFF_W2 + ib * W2_STR;
    const float* b0 = sm + OFF_B0 + ib * 8;
    const float* b1 = sm + OFF_B1 + ib * 8;
    const float* b2 = sm + OFF_B2 + ib * B2_STR;

    // L0 partial dots over own 16 inputs
    float pre[NS][8];
#pragma unroll
    for (int j = 0; j < 8; j++) {
        const float4* rp = (const float4*)(w0 + j * 36);
        ull c[8];
        ld4u(rp, c[0], c[1]); ld4u(rp + 1, c[2], c[3]);
        ld4u(rp + 2, c[4], c[5]); ld4u(rp + 3, c[6], c[7]);
#pragma unroll
        for (int si = 0; si < NS; si++) {
            ull m = 0ull;
#pragma unroll
            for (int p = 0; p < 8; p++) m = ffma2u(c[p], a[si][p], m);
            pre[si][j] = redu(m);
        }
    }
    ull h1p[NS][4];
#pragma unroll
    for (int si = 0; si < NS; si++) {
        ull pA = f2u(pre[si][0], pre[si][1]), pB = f2u(pre[si][2], pre[si][3]);
        ull pC = f2u(pre[si][4], pre[si][5]), pD = f2u(pre[si][6], pre[si][7]);
        pA = addx2(pA, shflxu(pA, 1)); pB = addx2(pB, shflxu(pB, 1));
        pC = addx2(pC, shflxu(pC, 1)); pD = addx2(pD, shflxu(pD, 1));
        float s0, s1, s2, s3, s4, s5, s6, s7;
        u2ff(pA, s0, s1); u2ff(pB, s2, s3); u2ff(pC, s4, s5); u2ff(pD, s6, s7);
        h1p[si][0] = f2u(tanhfast(b0[0] + s0), tanhfast(b0[1] + s1));
        h1p[si][1] = f2u(tanhfast(b0[2] + s2), tanhfast(b0[3] + s3));
        h1p[si][2] = f2u(tanhfast(b0[4] + s4), tanhfast(b0[5] + s5));
        h1p[si][3] = f2u(tanhfast(b0[6] + s6), tanhfast(b0[7] + s7));
    }

    // L1 fully local
    float g[NS][8];
#pragma unroll
    for (int j = 0; j < 8; j++) {
        const float4* rp = (const float4*)(w1 + j * 12);
        ull c0, c1, c2, c3; ld4u(rp, c0, c1); ld4u(rp + 1, c2, c3);
        float bb = b1[j];
#pragma unroll
        for (int si = 0; si < NS; si++) {
            ull m = ffma2u(c0, h1p[si][0], 0ull);
            m = ffma2u(c1, h1p[si][1], m);
            m = ffma2u(c2, h1p[si][2], m);
            m = ffma2u(c3, h1p[si][3], m);
            g[si][j] = tanhfast(bb + redu(m));
        }
    }
    ull h2p[NS][4];
#pragma unroll
    for (int si = 0; si < NS; si++)
#pragma unroll
        for (int p = 0; p < 4; p++) h2p[si][p] = f2u(g[si][2 * p], g[si][2 * p + 1]);

    // L2: own 16 rows (contiguous half), in pairs; role-exch ^2
#pragma unroll
    for (int q = 0; q < 8; q++) {
        const int i0 = jh * 16 + 2 * q;
        const float* r0 = w2 + i0 * 8 + jh * 4;
        ull c0, c1, c2, c3, d0, d1, d2, d3;
        ld4u((const float4*)r0, c0, c1); ld4u((const float4*)r0 + 1, c2, c3);
        ld4u((const float4*)(r0 + 8), d0, d1); ld4u((const float4*)(r0 + 8) + 1, d2, d3);
        float bb0 = b2[i0], bb1 = b2[i0 + 1];
        ull pk[NS];
#pragma unroll
        for (int si = 0; si < NS; si++) {
            ull m0 = ffma2u(c0, h2p[si][0], 0ull);
            m0 = ffma2u(c1, h2p[si][1], m0);
            m0 = ffma2u(c2, h2p[si][2], m0);
            m0 = ffma2u(c3, h2p[si][3], m0);
            ull m1 = ffma2u(d0, h2p[si][0], 0ull);
            m1 = ffma2u(d1, h2p[si][1], m1);
            m1 = ffma2u(d2, h2p[si][2], m1);
            m1 = ffma2u(d3, h2p[si][3], m1);
            float v0 = bb0 + redu(m0), v1 = bb1 + redu(m1);
            if (role) { v0 = __expf(v0); v1 = __expf(v1); }
            pk[si] = f2u(v0, v1);
        }
#pragma unroll
        for (int si = 0; si < NS; si++) {
            ull ot = shflxu(pk[si], 2);        // role partner, same jh
            float w0_, w1_, o0, o1;
            u2ff(pk[si], w0_, w1_); u2ff(ot, o0, o1);
            float t0 = role ? o0 : w0_, e0 = role ? w0_ : o0;
            float t1 = role ? o1 : w1_, e1 = role ? w1_ : o1;
            float vx, vy; u2ff(v[si][q], vx, vy);
            v[si][q] = f2u(fmaf(vx, e0, t0), fmaf(vy, e1, t1));
        }
    }
}

// ---------------- backward phase ------------------------------------------
//   u_new = (u - t(a)) * exp(-s(a));  yu = (yu - (J_t + diag(u-t) J_s) yd) * exp(-s)
// yd: y of the a-side (own jh-half, registers, read-only)
// yu: y of the u-side (own jh-half, registers, updated by BOTH roles —
//     after the ^2 exchange each lane holds the full (t, e^-s, cT, dS) set)
__device__ __forceinline__ void bwd_phase(const float* __restrict__ sm, int ibT,
                                          const ull (&a)[NS][8], ull (&u)[NS][8],
                                          const ull (&yd)[NS][8], ull (&yu)[NS][8],
                                          int role, int jh) {
    const int ib = ibT + role;
    const float* w0 = sm + OFF_W0 + ib * W0_STR + jh * 20;
    const float* w1 = sm + OFF_W1 + ib * W1_STR;
    const float* w2 = sm + OFF_W2 + ib * W2_STR;
    const float* b0 = sm + OFF_B0 + ib * 8;
    const float* b1 = sm + OFF_B1 + ib * 8;
    const float* b2 = sm + OFF_B2 + ib * B2_STR;

    // fused L0: hidden (a) + JVP (yd) partial dots — direction is register-local
    float preH[NS][8], preD[NS][8];
#pragma unroll
    for (int j = 0; j < 8; j++) {
        const float4* rp = (const float4*)(w0 + j * 36);
        ull c[8];
        ld4u(rp, c[0], c[1]); ld4u(rp + 1, c[2], c[3]);
        ld4u(rp + 2, c[4], c[5]); ld4u(rp + 3, c[6], c[7]);
#pragma unroll
        for (int si = 0; si < NS; si++) {
            ull mH = 0ull, mD = 0ull;
#pragma unroll
            for (int p = 0; p < 8; p++) {
                mH = ffma2u(c[p], a[si][p], mH);
                mD = ffma2u(c[p], yd[si][p], mD);
            }
            preH[si][j] = redu(mH); preD[si][j] = redu(mD);
        }
    }
    ull hO[NS][4], pO[NS][4];
#pragma unroll
    for (int si = 0; si < NS; si++) {
        ull hA = f2u(preH[si][0], preH[si][1]), hB = f2u(preH[si][2], preH[si][3]);
        ull hC = f2u(preH[si][4], preH[si][5]), hD = f2u(preH[si][6], preH[si][7]);
        ull dA_ = f2u(preD[si][0], preD[si][1]), dB = f2u(preD[si][2], preD[si][3]);
        ull dC = f2u(preD[si][4], preD[si][5]), dD = f2u(preD[si][6], preD[si][7]);
        hA = addx2(hA, shflxu(hA, 1)); hB = addx2(hB, shflxu(hB, 1));
        hC = addx2(hC, shflxu(hC, 1)); hD = addx2(hD, shflxu(hD, 1));
        dA_ = addx2(dA_, shflxu(dA_, 1)); dB = addx2(dB, shflxu(dB, 1));
        dC = addx2(dC, shflxu(dC, 1)); dD = addx2(dD, shflxu(dD, 1));
        float s[8], e[8];
        u2ff(hA, s[0], s[1]); u2ff(hB, s[2], s[3]); u2ff(hC, s[4], s[5]); u2ff(hD, s[6], s[7]);
        u2ff(dA_, e[0], e[1]); u2ff(dB, e[2], e[3]); u2ff(dC, e[4], e[5]); u2ff(dD, e[6], e[7]);
        float hv[8], pv[8];
#pragma unroll
        for (int j = 0; j < 8; j++) {
            float t = tanhfast(b0[j] + s[j]);
            hv[j] = t; pv[j] = (1.f - t * t) * e[j];
        }
#pragma unroll
        for (int p = 0; p < 4; p++) {
            hO[si][p] = f2u(hv[2 * p], hv[2 * p + 1]);
            pO[si][p] = f2u(pv[2 * p], pv[2 * p + 1]);
        }
    }

    // fused L1: fully local
    float gH[NS][8], gQ[NS][8];
#pragma unroll
    for (int j = 0; j < 8; j++) {
        const float4* rp = (const float4*)(w1 + j * 12);
        ull c0, c1, c2, c3; ld4u(rp, c0, c1); ld4u(rp + 1, c2, c3);
        float bb = b1[j];
#pragma unroll
        for (int si = 0; si < NS; si++) {
            ull mH = ffma2u(c0, hO[si][0], 0ull); mH = ffma2u(c1, hO[si][1], mH);
            mH = ffma2u(c2, hO[si][2], mH); mH = ffma2u(c3, hO[si][3], mH);
            ull mQ = ffma2u(c0, pO[si][0], 0ull); mQ = ffma2u(c1, pO[si][1], mQ);
            mQ = ffma2u(c2, pO[si][2], mQ); mQ = ffma2u(c3, pO[si][3], mQ);
            float t = tanhfast(bb + redu(mH));
            gH[si][j] = t; gQ[si][j] = (1.f - t * t) * redu(mQ);
        }
    }
    ull h2p[NS][4], qp[NS][4];
#pragma unroll
    for (int si = 0; si < NS; si++)
#pragma unroll
        for (int p = 0; p < 4; p++) {
            h2p[si][p] = f2u(gH[si][2 * p], gH[si][2 * p + 1]);
            qp[si][p]  = f2u(gQ[si][2 * p], gQ[si][2 * p + 1]);
        }

    // L2: own 16 rows in pairs; ^2 role exchange; u and yu updated in registers
#pragma unroll
    for (int q = 0; q < 8; q++) {
        const int i0 = jh * 16 + 2 * q;
        const float* r0 = w2 + i0 * 8 + jh * 4;
        ull c0, c1, c2, c3, d0, d1, d2, d3;
        ld4u((const float4*)r0, c0, c1); ld4u((const float4*)r0 + 1, c2, c3);
        ld4u((const float4*)(r0 + 8), d0, d1); ld4u((const float4*)(r0 + 8) + 1, d2, d3);
        float bb0 = b2[i0], bb1 = b2[i0 + 1];
        ull pkR[NS], pkX[NS];
#pragma unroll
        for (int si = 0; si < NS; si++) {
            ull m0 = ffma2u(c0, h2p[si][0], 0ull);
            m0 = ffma2u(c1, h2p[si][1], m0);
            m0 = ffma2u(c2, h2p[si][2], m0);
            m0 = ffma2u(c3, h2p[si][3], m0);
            ull m1 = ffma2u(d0, h2p[si][0], 0ull);
            m1 = ffma2u(d1, h2p[si][1], m1);
            m1 = ffma2u(d2, h2p[si][2], m1);
            m1 = ffma2u(d3, h2p[si][3], m1);
            ull x0 = ffma2u(c0, qp[si][0], 0ull);
            x0 = ffma2u(c1, qp[si][1], x0);
            x0 = ffma2u(c2, qp[si][2], x0);
            x0 = ffma2u(c3, qp[si][3], x0);
            ull x1 = ffma2u(d0, qp[si][0], 0ull);
            x1 = ffma2u(d1, qp[si][1], x1);
            x1 = ffma2u(d2, qp[si][2], x1);
            x1 = ffma2u(d3, qp[si][3], x1);
            float r0v = bb0 + redu(m0), r1v = bb1 + redu(m1);
            if (role) { r0v = __expf(-r0v); r1v = __expf(-r1v); }  // S sends e^{-s}
            pkR[si] = f2u(r0v, r1v);
            pkX[si] = f2u(redu(x0), redu(x1));
        }
#pragma unroll
        for (int si = 0; si < NS; si++) {
            ull oR = shflxu(pkR[si], 2);
            ull oX = shflxu(pkX[si], 2);
            float a0, a1, b0_, b1_, c0_, c1_, d0_, d1_;
            u2ff(pkR[si], a0, a1); u2ff(oR, b0_, b1_);
            u2ff(pkX[si], c0_, c1_); u2ff(oX, d0_, d1_);
            float tt0 = role ? b0_ : a0, ee0 = role ? a0 : b0_;
            float tt1 = role ? b1_ : a1, ee1 = role ? a1 : b1_;
            float cT0 = role ? d0_ : c0_, dS0 = role ? c0_ : d0_;
            float cT1 = role ? d1_ : c1_, dS1 = role ? c1_ : d1_;
            float ux, uy; u2ff(u[si][q], ux, uy);
            float dd0 = ux - tt0, dd1 = uy - tt1;      // = u_prev * e^{s}
            u[si][q] = f2u(dd0 * ee0, dd1 * ee1);
            // both roles update the replicated yu copy identically
            float yx, yy; u2ff(yu[si][q], yx, yy);
            float cv0 = cT0 + dd0 * dS0;
            float cv1 = cT1 + dd1 * dS1;
            yu[si][q] = f2u((yx - cv0) * ee0, (yy - cv1) * ee1);
        }
    }
}

__global__ __launch_bounds__(TPB, 1)
void nf12_kernel(const float* __restrict__ gX, const float* __restrict__ gXs,
                 const float* __restrict__ gW0, const float* __restrict__ gB0,
                 const float* __restrict__ gW1, const float* __restrict__ gB1,
                 const float* __restrict__ gW2, const float* __restrict__ gB2,
                 float* __restrict__ gOut) {
    extern __shared__ float sm[];
    const int tid = threadIdx.x;

    // cooperative weight load, skewed layouts
    for (int i = tid; i < 8192; i += TPB) {           // W0: 16|pad4|16 rows of 36
        int ib = i >> 8, j = (i >> 5) & 7, c = i & 31;
        sm[OFF_W0 + ib * W0_STR + j * 36 + c + (c >> 4) * 4] = gW0[i];
    }
    for (int i = tid; i < 2048; i += TPB) {           // W1: rows of 12
        int ib = i >> 6, j = (i >> 3) & 7, c = i & 7;
        sm[OFF_W1 + ib * W1_STR + j * 12 + c] = gW1[i];
    }
    for (int i = tid; i < 8192; i += TPB) {           // W2: +4 skew for rows>=16
        int ib = i >> 8, row = (i >> 3) & 31, c = i & 7;
        sm[OFF_W2 + ib * W2_STR + row * 8 + (row >> 4) * 4 + c] = gW2[i];
    }
    for (int i = tid; i < 256;  i += TPB) sm[OFF_B0 + i] = gB0[i];
    for (int i = tid; i < 256;  i += TPB) sm[OFF_B1 + i] = gB1[i];
    for (int i = tid; i < 1024; i += TPB) sm[OFF_B2 + (i >> 5) * B2_STR + (i & 31)] = gB2[i];
    __syncthreads();

    const int jh   = tid & 1;
    const int role = (tid >> 1) & 1;
    const int slot = tid >> 2;                  // 0..63
    const int s0   = blockIdx.x * SPB + slot;   // samples s0 + si*SLOTS

    // distributed state: own jh-half (16 floats) of lo/up, NS samples
    ull lo[NS][8], up[NS][8];
#pragma unroll
    for (int si = 0; si < NS; si++) {
        const float* base = gX + (size_t)(s0 + si * SLOTS) * 64;
        const float4* pl = (const float4*)(base + jh * 16);
        const float4* pu = (const float4*)(base + 32 + jh * 16);
#pragma unroll
        for (int qq = 0; qq < 4; qq++) {
            ld4u(pl + qq, lo[si][2 * qq], lo[si][2 * qq + 1]);
            ld4u(pu + qq, up[si][2 * qq], up[si][2 * qq + 1]);
        }
    }

    // ---------- forward: z = phi(x) ----------
    for (int k = 0; k < NF; k++) {
        fwd_phase(sm, k * 4 + 0, lo, up, role, jh);   // up' = t1(lo)+up*exp(s1(lo))
        fwd_phase(sm, k * 4 + 2, up, lo, role, jh);   // lo' = t2(up')+lo*exp(s2(up'))
    }

    // ---------- rhs in registers: g = -2 (x - x_star), own jh-half ----------
    ull ylo[NS][8], yup[NS][8];
#pragma unroll
    for (int si = 0; si < NS; si++) {
        const int samp = s0 + si * SLOTS;
        const float4* xl = (const float4*)(gX  + (size_t)samp * 64 + jh * 16);
        const float4* sl = (const float4*)(gXs + (size_t)samp * 64 + jh * 16);
        const float4* xu = (const float4*)(gX  + (size_t)samp * 64 + 32 + jh * 16);
        const float4* su = (const float4*)(gXs + (size_t)samp * 64 + 32 + jh * 16);
#pragma unroll
        for (int qq = 0; qq < 4; qq++) {
            float4 xa = xl[qq], xb = sl[qq];
            ylo[si][2 * qq]     = f2u(-2.f * (xa.x - xb.x), -2.f * (xa.y - xb.y));
            ylo[si][2 * qq + 1] = f2u(-2.f * (xa.z - xb.z), -2.f * (xa.w - xb.w));
            float4 ua = xu[qq], ub = su[qq];
            yup[si][2 * qq]     = f2u(-2.f * (ua.x - ub.x), -2.f * (ua.y - ub.y));
            yup[si][2 * qq + 1] = f2u(-2.f * (ua.z - ub.z), -2.f * (ua.w - ub.w));
        }
    }

    // ---------- backward: y <- J_k^{-1} y, all in registers ----------
    for (int k = NF - 1; k >= 0; k--) {
        bwd_phase(sm, k * 4 + 2, up, lo, yup, ylo, role, jh);  // invert lo-update
        bwd_phase(sm, k * 4 + 0, lo, up, ylo, yup, role, jh);  // invert up-update
    }

    // ---------- output: role 0 writes own jh-half of ylo/yup ----------
    if (role == 0) {
#pragma unroll
        for (int si = 0; si < NS; si++) {
            const int samp = s0 + si * SLOTS;
            float4* ol = (float4*)(gOut + (size_t)samp * 64 + jh * 16);
            float4* ou = (float4*)(gOut + (size_t)samp * 64 + 32 + jh * 16);
#pragma unroll
            for (int qq = 0; qq < 4; qq++) {
                float a0, a1, a2, a3;
                u2ff(ylo[si][2 * qq], a0, a1); u2ff(ylo[si][2 * qq + 1], a2, a3);
                ol[qq] = make_float4(a0, a1, a2, a3);
                u2ff(yup[si][2 * qq], a0, a1); u2ff(yup[si][2 * qq + 1], a2, a3);
                ou[qq] = make_float4(a0, a1, a2, a3);
            }
        }
    }
}

extern "C" void kernel_launch(void* const* d_in, const int* in_sizes, int n_in,
                              void* d_out, int out_size) {
    const float* x  = (const float*)d_in[0];
    const float* xs = (const float*)d_in[1];
    const float* W0 = (const float*)d_in[2];
    const float* b0 = (const float*)d_in[3];
    const float* W1 = (const float*)d_in[4];
    const float* b1 = (const float*)d_in[5];
    const float* W2 = (const float*)d_in[6];
    const float* b2 = (const float*)d_in[7];
    float* out = (float*)d_out;

    cudaFuncSetAttribute(nf12_kernel, cudaFuncAttributeMaxDynamicSharedMemorySize, SMEM_BYTES);
    nf12_kernel<<<BSZ / SPB, TPB, SMEM_BYTES>>>(x, xs, W0, b0, W1, b1, W2, b2, out);
}